// round 13
// baseline (speedup 1.0000x reference)
#include <cuda_runtime.h>
#include <cuda.h>
#include <math.h>
#include <stdint.h>

// Scratch: one full-size intermediate buffer (B*M*N floats = 134 MB).
#define SCRATCH_ELEMS (2ull * 4096ull * 4096ull)
__device__ float g_scratch[SCRATCH_ELEMS];

#define NN 4096
#define HH 2048

// ---- packed f32x2 complex add/sub (sm_103a) ----
__device__ __forceinline__ float2 cadd(float2 a, float2 b){
    unsigned long long ua, ub, ur;
    asm("mov.b64 %0, {%1,%2};" : "=l"(ua) : "f"(a.x), "f"(a.y));
    asm("mov.b64 %0, {%1,%2};" : "=l"(ub) : "f"(b.x), "f"(b.y));
    asm("add.rn.f32x2 %0, %1, %2;" : "=l"(ur) : "l"(ua), "l"(ub));
    float2 r;
    asm("mov.b64 {%0,%1}, %2;" : "=f"(r.x), "=f"(r.y) : "l"(ur));
    return r;
}
__device__ __forceinline__ float2 csub(float2 a, float2 b){
    unsigned long long ua, ub, ur;
    asm("mov.b64 %0, {%1,%2};" : "=l"(ua) : "f"(a.x), "f"(a.y));
    asm("mov.b64 %0, {%1,%2};" : "=l"(ub) : "f"(b.x), "f"(b.y));
    asm("sub.rn.f32x2 %0, %1, %2;" : "=l"(ur) : "l"(ua), "l"(ub));
    float2 r;
    asm("mov.b64 {%0,%1}, %2;" : "=f"(r.x), "=f"(r.y) : "l"(ur));
    return r;
}
__device__ __forceinline__ float2 cmul(float2 a, float2 b){
    return make_float2(fmaf(a.x, b.x, -a.y*b.y), fmaf(a.x, b.y, a.y*b.x));
}
__device__ __forceinline__ float2 mulip(float2 a){ return make_float2(-a.y, a.x); }

__device__ __forceinline__ uint32_t smem_u32(const void* p){
    uint32_t a;
    asm("{ .reg .u64 t; cvta.to.shared.u64 t, %1; cvt.u32.u64 %0, t; }" : "=r"(a) : "l"(p));
    return a;
}

// Pad one float2 every 16.
#define PIDX(a) ((a) + ((a) >> 4))
#define PBUF (HH + (HH >> 4))   // 2176 float2

// ---- 16-point inverse DFT in registers ----
__device__ __forceinline__ void r16_bfly(float2 g[16]) {
    const float C8 = 0.70710678118654752f;
    const float2 W1 = make_float2( 0.92387953251128674f,  0.38268343236508978f);
    const float2 W2 = make_float2( C8,  C8);
    const float2 W3 = make_float2( 0.38268343236508978f,  0.92387953251128674f);
    const float2 W6 = make_float2(-C8,  C8);
    const float2 W9 = make_float2(-0.92387953251128674f, -0.38268343236508978f);
    float2 c[16];
#pragma unroll
    for (int t0 = 0; t0 < 4; t0++) {
        float2 x0 = g[t0], x1 = g[t0+4], x2 = g[t0+8], x3 = g[t0+12];
        float2 s02 = cadd(x0,x2), d02 = csub(x0,x2);
        float2 s13 = cadd(x1,x3), d13 = csub(x1,x3);
        float2 id13 = mulip(d13);
        c[t0*4+0] = cadd(s02,s13);
        c[t0*4+1] = cadd(d02,id13);
        c[t0*4+2] = csub(s02,s13);
        c[t0*4+3] = csub(d02,id13);
    }
    c[5]  = cmul(c[5],  W1);
    c[6]  = cmul(c[6],  W2);
    c[7]  = cmul(c[7],  W3);
    c[9]  = cmul(c[9],  W2);
    c[10] = mulip(c[10]);
    c[11] = cmul(c[11], W6);
    c[13] = cmul(c[13], W3);
    c[14] = cmul(c[14], W6);
    c[15] = cmul(c[15], W9);
#pragma unroll
    for (int u0 = 0; u0 < 4; u0++) {
        float2 x0 = c[u0], x1 = c[4+u0], x2 = c[8+u0], x3 = c[12+u0];
        float2 s02 = cadd(x0,x2), d02 = csub(x0,x2);
        float2 s13 = cadd(x1,x3), d13 = csub(x1,x3);
        float2 id13 = mulip(d13);
        g[u0]    = cadd(s02,s13);
        g[u0+4]  = cadd(d02,id13);
        g[u0+8]  = csub(s02,s13);
        g[u0+12] = csub(d02,id13);
    }
}

// ---- 8-point inverse DFT in registers ----
__device__ __forceinline__ void r8_bfly(float2 a[8]) {
    const float C8 = 0.70710678118654752f;
    float2 e0 = cadd(a[0],a[4]), e1 = cadd(a[1],a[5]);
    float2 e2 = cadd(a[2],a[6]), e3 = cadd(a[3],a[7]);
    float2 o0 = csub(a[0],a[4]), o1 = csub(a[1],a[5]);
    float2 o2 = csub(a[2],a[6]), o3 = csub(a[3],a[7]);
    o1 = make_float2(C8*(o1.x - o1.y),  C8*(o1.x + o1.y));
    o2 = mulip(o2);
    o3 = make_float2(-C8*(o3.x + o3.y), C8*(o3.x - o3.y));
    float2 t0 = cadd(e0,e2), t1 = csub(e0,e2);
    float2 t2 = cadd(e1,e3), t3 = csub(e1,e3);
    float2 it3 = mulip(t3);
    float2 u0 = cadd(o0,o2), u1 = csub(o0,o2);
    float2 u2 = cadd(o1,o3), u3 = csub(o1,o3);
    float2 iu3 = mulip(u3);
    a[0] = cadd(t0,t2);  a[4] = csub(t0,t2);
    a[2] = cadd(t1,it3); a[6] = csub(t1,it3);
    a[1] = cadd(u0,u2);  a[5] = csub(u0,u2);
    a[3] = cadd(u1,iu3); a[7] = csub(u1,iu3);
}

// ---------------------------------------------------------------------------
// Row FFT kernel (round-10 proven): 128 thr, 1 row/CTA, radix 16/16/8.
// MODE 0 = IDCT-II inverse, MODE 1 = IDXST.
// ---------------------------------------------------------------------------
template <int MODE>
__global__ __launch_bounds__(128, 4)
void dct_fft_kernel(const float* __restrict__ in,
                    const float2* __restrict__ expk,
                    float* __restrict__ out) {
    __shared__ __align__(16) float2 sX[PBUF];
    __shared__ __align__(16) float2 sY[PBUF];
    float* xs = (float*)sX;

    const int idx = threadIdx.x;
    const size_t base = (size_t)blockIdx.x * (size_t)NN;

    {
        const float4* in4 = (const float4*)(in + base);
        float4* xs4 = (float4*)xs;
#pragma unroll
        for (int i = idx; i < NN/4; i += 128) xs4[i] = in4[i];
    }
    __syncthreads();

    {
        float2 g[16];
        const float2 E32 = make_float2(0.98078528040323044f, 0.19509032201612827f);
        float sn, cs;
        __sincosf((float)(2.0*M_PI/4096.0) * (float)idx, &sn, &cs);
        float2 w = make_float2(cs, sn);
#pragma unroll
        for (int t = 0; t < 16; t++) {
            const int j = idx + 128*t;
            float Xa0, Xb0, Xa1, Xb1;
            if (MODE == 0) {
                Xa0 = xs[j];
                Xb0 = (j == 0) ? 0.0f : xs[NN - j];
                Xa1 = xs[j + HH];
                Xb1 = xs[(j == 0) ? HH : (HH - j)];
            } else {
                Xa0 = (j == 0) ? 0.0f : xs[NN - j];
                Xb0 = (j == 0) ? 0.0f : xs[j];
                Xa1 = xs[(j == 0) ? HH : (HH - j)];
                Xb1 = xs[j + HH];
            }
            const float2 ea = expk[j];
            const float2 eb = expk[j + HH];
            float2 V0 = make_float2(0.5f*(Xa0*ea.x + Xb0*ea.y),
                                    0.5f*(Xa0*ea.y - Xb0*ea.x));
            float2 V1 = make_float2(0.5f*(Xa1*eb.x + Xb1*eb.y),
                                    0.5f*(Xa1*eb.y - Xb1*eb.x));
            float2 S = cadd(V0, V1);
            float2 D = csub(V0, V1);
            float2 wd = cmul(w, D);
            g[t] = make_float2(S.x - wd.y, S.y + wd.x);
            w = cmul(w, E32);
        }
        r16_bfly(g);
        __sincosf((float)(2.0*M_PI/2048.0) * (float)idx, &sn, &cs);
        const float2 w1 = make_float2(cs, sn);
        sY[PIDX(16*idx)] = g[0];
        float2 wu = w1;
#pragma unroll
        for (int u = 1; u < 16; u++) {
            sY[PIDX(16*idx + u)] = cmul(g[u], wu);
            wu = cmul(wu, w1);
        }
    }
    __syncthreads();

    {
        float2 g[16];
#pragma unroll
        for (int t = 0; t < 16; t++) g[t] = sY[PIDX(idx + 128*t)];
        r16_bfly(g);
        const int p = idx >> 4, j = idx & 15;
        float sn, cs;
        __sincosf((float)(2.0*M_PI/128.0) * (float)p, &sn, &cs);
        const float2 w1 = make_float2(cs, sn);
        const int ob = j + 256*p;
        sX[PIDX(ob)] = g[0];
        float2 wu = w1;
#pragma unroll
        for (int u = 1; u < 16; u++) {
            sX[PIDX(ob + 16*u)] = cmul(g[u], wu);
            wu = cmul(wu, w1);
        }
    }
    __syncthreads();

    {
        const int b1 = idx, b2 = 255 - idx;
        float2 A[8], Bv[8];
#pragma unroll
        for (int u = 0; u < 8; u++) A[u]  = sX[PIDX(b1 + 256*u)];
#pragma unroll
        for (int u = 0; u < 8; u++) Bv[u] = sX[PIDX(b2 + 256*u)];
        r8_bfly(A);
        r8_bfly(Bv);
        const float sgn = (MODE == 1) ? -1.0f : 1.0f;
        float4* out4 = (float4*)(out + base);
#pragma unroll
        for (int u = 0; u < 4; u++) {
            float2 z1 = A[u], z2 = Bv[7-u];
            out4[b1 + 256*u] = make_float4(z1.x, sgn*z2.y, z1.y, sgn*z2.x);
            z1 = Bv[u]; z2 = A[7-u];
            out4[b2 + 256*u] = make_float4(z1.x, sgn*z2.y, z1.y, sgn*z2.x);
        }
    }
}

// ---------------------------------------------------------------------------
// Batched transpose (B, R, C) -> (B, C, R): 64x64 tiles, 256 threads, float4.
// ---------------------------------------------------------------------------
__global__ __launch_bounds__(256)
void transpose_kernel(const float* __restrict__ in, float* __restrict__ out,
                      int R, int C) {
    __shared__ float tile[64][65];
    const int tx = threadIdx.x & 15;
    const int ty = threadIdx.x >> 4;
    const size_t off = (size_t)blockIdx.z * (size_t)R * (size_t)C;
    const int c0 = blockIdx.x * 64;
    const int r0 = blockIdx.y * 64;

#pragma unroll
    for (int k = 0; k < 4; k++) {
        const int r = ty + 16*k;
        const float4 v = *(const float4*)(in + off + (size_t)(r0 + r)*C + (c0 + 4*tx));
        tile[r][4*tx+0] = v.x;
        tile[r][4*tx+1] = v.y;
        tile[r][4*tx+2] = v.z;
        tile[r][4*tx+3] = v.w;
    }
    __syncthreads();
#pragma unroll
    for (int k = 0; k < 4; k++) {
        const int r = ty + 16*k;
        float4 v;
        v.x = tile[4*tx+0][r];
        v.y = tile[4*tx+1][r];
        v.z = tile[4*tx+2][r];
        v.w = tile[4*tx+3][r];
        *(float4*)(out + off + (size_t)(c0 + r)*R + (r0 + 4*tx)) = v;
    }
}

// ===========================================================================
// Pass 3 (3-pass path): IDCT along M on rows of the transposed intermediate
// (B, N, M); output written TRANSPOSED into row-major d_out (B, M, N) via
// TMA stores (8-col x 256-row boxes). 8 rows/CTA, 1024 threads, round-6 FFT
// core (r8/r8/r8/r4 in-place, 64 regs).
// ===========================================================================
#define CSTRIDE_F 4356

template <int S>
__device__ __forceinline__ void r8_stage_ip(float2* zb, int t) {
    float2 A[2][8];
#pragma unroll
    for (int h = 0; h < 2; h++) {
        const int idx = t + 128*h;
#pragma unroll
        for (int u = 0; u < 8; u++) A[h][u] = zb[PIDX(idx + 256*u)];
    }
    __syncthreads();
#pragma unroll
    for (int h = 0; h < 2; h++) {
        const int idx = t + 128*h;
        r8_bfly(A[h]);
        const int p = idx / S, j = idx - p*S;
        float sn, cs;
        __sincosf((float)(2.0*M_PI*(double)S/2048.0) * (float)p, &sn, &cs);
        const float2 w1 = make_float2(cs, sn);
        const int ob = j + 8*S*p;
        zb[PIDX(ob)] = A[h][0];
        float2 wu = w1;
#pragma unroll
        for (int u = 1; u < 8; u++) {
            zb[PIDX(ob + u*S)] = cmul(A[h][u], wu);
            wu = cmul(wu, w1);
        }
    }
    __syncthreads();
}

__global__ __launch_bounds__(1024, 1)
void idct_row_tma_kernel(const __grid_constant__ CUtensorMap tmap,
                         const float* __restrict__ in,    // (B, N, M)
                         const float2* __restrict__ expk) {
    extern __shared__ __align__(16) float smf[];
    const int tid = threadIdx.x;
    const int b  = blockIdx.x >> 9;           // 512 CTAs per batch
    const int n0 = (blockIdx.x & 511) << 3;   // 8 rows (n values) per CTA
    const int lr = tid >> 7;                  // local row 0..7
    const int t  = tid & 127;

    // ---- load 8 rows, fully coalesced float4 ----
    {
        const float4* src = (const float4*)(in + (size_t)b*NN*NN + (size_t)(n0 + lr)*NN);
        float4* dst = (float4*)(smf + lr*CSTRIDE_F);
#pragma unroll
        for (int k = 0; k < 8; k++) dst[t + 128*k] = src[t + 128*k];
    }
    __syncthreads();

    float* xs = smf + lr*CSTRIDE_F;
    float2* zb = (float2*)xs;

    // ---- prologue: G (IDCT form), registers (round-6 proven) ----
    float2 G[16];
    {
        const float2 STEP = make_float2(0.98078528040323044f, 0.19509032201612827f); // e^{2pi i/32}
        float sn, cs;
        __sincosf((float)(2.0*M_PI/4096.0) * (float)t, &sn, &cs);
        float2 w = make_float2(cs, sn);
#pragma unroll
        for (int k = 0; k < 16; k++) {
            const int j = t + 128*k;
            const float Xa0 = xs[j];
            const float Xb0 = (j == 0) ? 0.0f : xs[NN - j];
            const float Xa1 = xs[j + HH];
            const float Xb1 = xs[(j == 0) ? HH : (HH - j)];
            const float2 ea = expk[j];
            const float2 eb = expk[j + HH];
            float2 V0 = make_float2(0.5f*(Xa0*ea.x + Xb0*ea.y),
                                    0.5f*(Xa0*ea.y - Xb0*ea.x));
            float2 V1 = make_float2(0.5f*(Xa1*eb.x + Xb1*eb.y),
                                    0.5f*(Xa1*eb.y - Xb1*eb.x));
            float2 S = cadd(V0, V1);
            float2 D = csub(V0, V1);
            float2 wd = cmul(w, D);
            G[k] = make_float2(S.x - wd.y, S.y + wd.x);
            w = cmul(w, STEP);
        }
    }
    __syncthreads();   // all xs reads done before stage-1 writes

    // ---- stage 1: radix-8, S=1 from G ----
#pragma unroll
    for (int h = 0; h < 2; h++) {
        float2 a[8];
#pragma unroll
        for (int u = 0; u < 8; u++) a[u] = G[h + 2*u];
        r8_bfly(a);
        const int idx = t + 128*h;
        float sn, cs;
        __sincosf((float)(2.0*M_PI/2048.0) * (float)idx, &sn, &cs);
        const float2 w1 = make_float2(cs, sn);
        zb[PIDX(8*idx)] = a[0];
        float2 wu = w1;
#pragma unroll
        for (int u = 1; u < 8; u++) {
            zb[PIDX(8*idx + u)] = cmul(a[u], wu);
            wu = cmul(wu, w1);
        }
    }
    __syncthreads();

    r8_stage_ip<8>(zb, t);
    r8_stage_ip<64>(zb, t);

    // ---- stage 4: radix-4, S=512, per-thread private slots ----
#pragma unroll
    for (int h = 0; h < 4; h++) {
        const int idx = t + 128*h;
        float2 a0 = zb[PIDX(idx)],        a1 = zb[PIDX(idx + 512)];
        float2 a2 = zb[PIDX(idx + 1024)], a3 = zb[PIDX(idx + 1536)];
        float2 t0 = cadd(a0,a2), t1 = csub(a0,a2);
        float2 t2 = cadd(a1,a3), t3 = csub(a1,a3);
        float2 it3 = mulip(t3);
        zb[PIDX(idx)]        = cadd(t0,t2);
        zb[PIDX(idx + 512)]  = cadd(t1,it3);
        zb[PIDX(idx + 1024)] = csub(t0,t2);
        zb[PIDX(idx + 1536)] = csub(t1,it3);
    }
    __syncthreads();

    // ---- de-interleave into staging tile [2048 m][8 cols], TMA store x2 ----
    float* stage = smf + 8*CSTRIDE_F;
    const uint32_t stage_addr = smem_u32(stage);
    const float2* zc = (const float2*)(smf + lr*CSTRIDE_F);
#pragma unroll 1
    for (int half = 0; half < 2; half++) {
        const int mbase = half << 11;
#pragma unroll
        for (int k = 0; k < 16; k++) {
            const int mm = mbase + t + 128*k;
            const int vidx = (mm & 1) ? (4095 - (mm >> 1)) : (mm >> 1);
            const float2 z = zc[PIDX(vidx >> 1)];
            stage[((mm - mbase) << 3) + lr] = (vidx & 1) ? z.y : z.x;
        }
        __syncthreads();
        if (tid == 0) {
            asm volatile("fence.proxy.async;" ::: "memory");
#pragma unroll
            for (int i = 0; i < 8; i++) {
                asm volatile(
                    "cp.async.bulk.tensor.3d.global.shared::cta.tile.bulk_group "
                    "[%0, {%1, %2, %3}], [%4];"
                    :: "l"(&tmap), "r"(n0), "r"(mbase + 256*i), "r"(b),
                       "r"(stage_addr + (uint32_t)(i * 8192))
                    : "memory");
            }
            asm volatile("cp.async.bulk.commit_group;" ::: "memory");
            asm volatile("cp.async.bulk.wait_group 0;" ::: "memory");
        }
        __syncthreads();
    }
}

// ---------------------------------------------------------------------------
// Host side
// ---------------------------------------------------------------------------
typedef CUresult (CUDAAPI *encode_fn_t)(
    CUtensorMap*, CUtensorMapDataType, cuuint32_t, void*,
    const cuuint64_t*, const cuuint64_t*, const cuuint32_t*, const cuuint32_t*,
    CUtensorMapInterleave, CUtensorMapSwizzle, CUtensorMapL2promotion,
    CUtensorMapFloatOOBfill);

static encode_fn_t get_encode_fn() {
    static encode_fn_t fn = nullptr;
    static bool tried = false;
    if (!tried) {
        tried = true;
        void* p = nullptr;
        cudaDriverEntryPointQueryResult qr;
        if (cudaGetDriverEntryPointByVersion("cuTensorMapEncodeTiled", &p, 12000,
                                             cudaEnableDefault, &qr) == cudaSuccess &&
            qr == cudaDriverEntryPointSuccess) {
            fn = (encode_fn_t)p;
        }
    }
    return fn;
}

extern "C" void kernel_launch(void* const* d_in, const int* in_sizes, int n_in,
                              void* d_out, int out_size) {
    const float*  x     = (const float*)d_in[0];
    const float2* expkM = (const float2*)d_in[1];
    const float2* expkN = (const float2*)d_in[2];
    const int M = in_sizes[1] / 2;            // 4096
    const int N = in_sizes[2] / 2;            // 4096
    const int B = in_sizes[0] / (M * N);      // 2
    float* out = (float*)d_out;

    float* scratch = nullptr;
    cudaGetSymbolAddress((void**)&scratch, g_scratch);

    // Try to build the TMA descriptor for d_out (B, M, N) fp32.
    alignas(64) static CUtensorMap tmap;
    bool use_tma = false;
    encode_fn_t enc = get_encode_fn();
    if (enc) {
        cuuint64_t dims[3]    = {(cuuint64_t)N, (cuuint64_t)M, (cuuint64_t)B};
        cuuint64_t strides[2] = {(cuuint64_t)N * 4, (cuuint64_t)M * N * 4};
        cuuint32_t box[3]     = {8, 256, 1};
        cuuint32_t estr[3]    = {1, 1, 1};
        use_tma = (enc(&tmap, CU_TENSOR_MAP_DATA_TYPE_FLOAT32, 3, d_out,
                       dims, strides, box, estr,
                       CU_TENSOR_MAP_INTERLEAVE_NONE, CU_TENSOR_MAP_SWIZZLE_NONE,
                       CU_TENSOR_MAP_L2_PROMOTION_L2_128B,
                       CU_TENSOR_MAP_FLOAT_OOB_FILL_NONE) == CUDA_SUCCESS);
    }

    if (use_tma) {
        // ---- 3-pass path ----
        // Pass 1: IDXST along N (rows of x) -> d_out used as temp (B, M, N)
        dct_fft_kernel<1><<<B * M, 128>>>(x, expkN, out);
        // Pass 2: transpose (B, M, N) -> (B, N, M): d_out -> scratch
        {
            dim3 grid(N / 64, M / 64, B), blk(256);
            transpose_kernel<<<grid, blk>>>(out, scratch, M, N);
        }
        // Pass 3: IDCT along M (rows of scratch), TMA-store transposed -> d_out
        const int smem3 = 8 * CSTRIDE_F * 4 + 2048 * 8 * 4;   // 204928 B
        cudaFuncSetAttribute(idct_row_tma_kernel,
                             cudaFuncAttributeMaxDynamicSharedMemorySize, smem3);
        idct_row_tma_kernel<<<B * (N / 8), 1024, smem3>>>(tmap, scratch, expkM);
    } else {
        // ---- 4-pass fallback (proven) ----
        dct_fft_kernel<1><<<B * M, 128>>>(x, expkN, scratch);
        {
            dim3 grid(N / 64, M / 64, B), blk(256);
            transpose_kernel<<<grid, blk>>>(scratch, out, M, N);
        }
        dct_fft_kernel<0><<<B * N, 128>>>(out, expkM, scratch);
        {
            dim3 grid(M / 64, N / 64, B), blk(256);
            transpose_kernel<<<grid, blk>>>(scratch, out, N, M);
        }
    }
}

// round 14
// speedup vs baseline: 1.3783x; 1.3783x over previous
#include <cuda_runtime.h>
#include <math.h>

// Two full-size intermediates (134 MB each) to break pipeline aliasing.
#define SCRATCH_ELEMS (2ull * 4096ull * 4096ull)
__device__ float g_scratch1[SCRATCH_ELEMS];
__device__ float g_scratch2[SCRATCH_ELEMS];

#define NN 4096
#define HH 2048

__device__ __forceinline__ float2 cadd(float2 a, float2 b){ return make_float2(a.x+b.x, a.y+b.y); }
__device__ __forceinline__ float2 csub(float2 a, float2 b){ return make_float2(a.x-b.x, a.y-b.y); }
__device__ __forceinline__ float2 cmul(float2 a, float2 b){
    return make_float2(fmaf(a.x, b.x, -a.y*b.y), fmaf(a.x, b.y, a.y*b.x));
}
__device__ __forceinline__ float2 mulip(float2 a){ return make_float2(-a.y, a.x); }  // * (+i)

// Pad one float2 every 16.
#define PIDX(a) ((a) + ((a) >> 4))
#define PBUF (HH + (HH >> 4))   // 2176 float2

// ---- 16-point inverse DFT in registers ----
__device__ __forceinline__ void r16_bfly(float2 g[16]) {
    const float C8 = 0.70710678118654752f;
    const float2 W1 = make_float2( 0.92387953251128674f,  0.38268343236508978f);
    const float2 W2 = make_float2( C8,  C8);
    const float2 W3 = make_float2( 0.38268343236508978f,  0.92387953251128674f);
    const float2 W6 = make_float2(-C8,  C8);
    const float2 W9 = make_float2(-0.92387953251128674f, -0.38268343236508978f);
    float2 c[16];
#pragma unroll
    for (int t0 = 0; t0 < 4; t0++) {
        float2 x0 = g[t0], x1 = g[t0+4], x2 = g[t0+8], x3 = g[t0+12];
        float2 s02 = cadd(x0,x2), d02 = csub(x0,x2);
        float2 s13 = cadd(x1,x3), d13 = csub(x1,x3);
        float2 id13 = mulip(d13);
        c[t0*4+0] = cadd(s02,s13);
        c[t0*4+1] = cadd(d02,id13);
        c[t0*4+2] = csub(s02,s13);
        c[t0*4+3] = csub(d02,id13);
    }
    c[5]  = cmul(c[5],  W1);
    c[6]  = cmul(c[6],  W2);
    c[7]  = cmul(c[7],  W3);
    c[9]  = cmul(c[9],  W2);
    c[10] = mulip(c[10]);
    c[11] = cmul(c[11], W6);
    c[13] = cmul(c[13], W3);
    c[14] = cmul(c[14], W6);
    c[15] = cmul(c[15], W9);
#pragma unroll
    for (int u0 = 0; u0 < 4; u0++) {
        float2 x0 = c[u0], x1 = c[4+u0], x2 = c[8+u0], x3 = c[12+u0];
        float2 s02 = cadd(x0,x2), d02 = csub(x0,x2);
        float2 s13 = cadd(x1,x3), d13 = csub(x1,x3);
        float2 id13 = mulip(d13);
        g[u0]    = cadd(s02,s13);
        g[u0+4]  = cadd(d02,id13);
        g[u0+8]  = csub(s02,s13);
        g[u0+12] = csub(d02,id13);
    }
}

// ---- 8-point inverse DFT in registers ----
__device__ __forceinline__ void r8_bfly(float2 a[8]) {
    const float C8 = 0.70710678118654752f;
    float2 e0 = cadd(a[0],a[4]), e1 = cadd(a[1],a[5]);
    float2 e2 = cadd(a[2],a[6]), e3 = cadd(a[3],a[7]);
    float2 o0 = csub(a[0],a[4]), o1 = csub(a[1],a[5]);
    float2 o2 = csub(a[2],a[6]), o3 = csub(a[3],a[7]);
    o1 = make_float2(C8*(o1.x - o1.y),  C8*(o1.x + o1.y));
    o2 = mulip(o2);
    o3 = make_float2(-C8*(o3.x + o3.y), C8*(o3.x - o3.y));
    float2 t0 = cadd(e0,e2), t1 = csub(e0,e2);
    float2 t2 = cadd(e1,e3), t3 = csub(e1,e3);
    float2 it3 = mulip(t3);
    float2 u0 = cadd(o0,o2), u1 = csub(o0,o2);
    float2 u2 = cadd(o1,o3), u3 = csub(o1,o3);
    float2 iu3 = mulip(u3);
    a[0] = cadd(t0,t2);  a[4] = csub(t0,t2);
    a[2] = cadd(t1,it3); a[6] = csub(t1,it3);
    a[1] = cadd(u0,u2);  a[5] = csub(u0,u2);
    a[3] = cadd(u1,iu3); a[7] = csub(u1,iu3);
}

// ---------------------------------------------------------------------------
// Row FFT kernel (round-10 proven): 128 thr, 1 row/CTA, radix 16/16/8.
// MODE 0 = IDCT-II inverse, MODE 1 = IDXST. Safe for row-wise in-place use
// (all global loads complete before any global store).
// ---------------------------------------------------------------------------
template <int MODE>
__global__ __launch_bounds__(128, 4)
void dct_fft_kernel(const float* __restrict__ in,
                    const float2* __restrict__ expk,
                    float* __restrict__ out) {
    __shared__ __align__(16) float2 sX[PBUF];
    __shared__ __align__(16) float2 sY[PBUF];
    float* xs = (float*)sX;

    const int idx = threadIdx.x;
    const size_t base = (size_t)blockIdx.x * (size_t)NN;

    {
        const float4* in4 = (const float4*)(in + base);
        float4* xs4 = (float4*)xs;
#pragma unroll
        for (int i = idx; i < NN/4; i += 128) xs4[i] = in4[i];
    }
    __syncthreads();

    {
        float2 g[16];
        const float2 E32 = make_float2(0.98078528040323044f, 0.19509032201612827f);
        float sn, cs;
        __sincosf((float)(2.0*M_PI/4096.0) * (float)idx, &sn, &cs);
        float2 w = make_float2(cs, sn);
#pragma unroll
        for (int t = 0; t < 16; t++) {
            const int j = idx + 128*t;
            float Xa0, Xb0, Xa1, Xb1;
            if (MODE == 0) {
                Xa0 = xs[j];
                Xb0 = (j == 0) ? 0.0f : xs[NN - j];
                Xa1 = xs[j + HH];
                Xb1 = xs[(j == 0) ? HH : (HH - j)];
            } else {
                Xa0 = (j == 0) ? 0.0f : xs[NN - j];
                Xb0 = (j == 0) ? 0.0f : xs[j];
                Xa1 = xs[(j == 0) ? HH : (HH - j)];
                Xb1 = xs[j + HH];
            }
            const float2 ea = expk[j];
            const float2 eb = expk[j + HH];
            float2 V0 = make_float2(0.5f*(Xa0*ea.x + Xb0*ea.y),
                                    0.5f*(Xa0*ea.y - Xb0*ea.x));
            float2 V1 = make_float2(0.5f*(Xa1*eb.x + Xb1*eb.y),
                                    0.5f*(Xa1*eb.y - Xb1*eb.x));
            float2 S = cadd(V0, V1);
            float2 D = csub(V0, V1);
            float2 wd = cmul(w, D);
            g[t] = make_float2(S.x - wd.y, S.y + wd.x);
            w = cmul(w, E32);
        }
        r16_bfly(g);
        __sincosf((float)(2.0*M_PI/2048.0) * (float)idx, &sn, &cs);
        const float2 w1 = make_float2(cs, sn);
        sY[PIDX(16*idx)] = g[0];
        float2 wu = w1;
#pragma unroll
        for (int u = 1; u < 16; u++) {
            sY[PIDX(16*idx + u)] = cmul(g[u], wu);
            wu = cmul(wu, w1);
        }
    }
    __syncthreads();

    {
        float2 g[16];
#pragma unroll
        for (int t = 0; t < 16; t++) g[t] = sY[PIDX(idx + 128*t)];
        r16_bfly(g);
        const int p = idx >> 4, j = idx & 15;
        float sn, cs;
        __sincosf((float)(2.0*M_PI/128.0) * (float)p, &sn, &cs);
        const float2 w1 = make_float2(cs, sn);
        const int ob = j + 256*p;
        sX[PIDX(ob)] = g[0];
        float2 wu = w1;
#pragma unroll
        for (int u = 1; u < 16; u++) {
            sX[PIDX(ob + 16*u)] = cmul(g[u], wu);
            wu = cmul(wu, w1);
        }
    }
    __syncthreads();

    {
        const int b1 = idx, b2 = 255 - idx;
        float2 A[8], Bv[8];
#pragma unroll
        for (int u = 0; u < 8; u++) A[u]  = sX[PIDX(b1 + 256*u)];
#pragma unroll
        for (int u = 0; u < 8; u++) Bv[u] = sX[PIDX(b2 + 256*u)];
        r8_bfly(A);
        r8_bfly(Bv);
        const float sgn = (MODE == 1) ? -1.0f : 1.0f;
        float4* out4 = (float4*)(out + base);
#pragma unroll
        for (int u = 0; u < 4; u++) {
            float2 z1 = A[u], z2 = Bv[7-u];
            out4[b1 + 256*u] = make_float4(z1.x, sgn*z2.y, z1.y, sgn*z2.x);
            z1 = Bv[u]; z2 = A[7-u];
            out4[b2 + 256*u] = make_float4(z1.x, sgn*z2.y, z1.y, sgn*z2.x);
        }
    }
}

// ---------------------------------------------------------------------------
// Chunked transpose R x C -> C x R: 64x64 tiles, 256 threads, float4,
// with tile-origin offsets for pipelined chunking.
// ---------------------------------------------------------------------------
__global__ __launch_bounds__(256)
void transpose_kernel(const float* __restrict__ in, float* __restrict__ out,
                      int R, int C, int c0_base, int r0_base) {
    __shared__ float tile[64][65];
    const int tx = threadIdx.x & 15;
    const int ty = threadIdx.x >> 4;
    const int c0 = c0_base + blockIdx.x * 64;
    const int r0 = r0_base + blockIdx.y * 64;

#pragma unroll
    for (int k = 0; k < 4; k++) {
        const int r = ty + 16*k;
        const float4 v = *(const float4*)(in + (size_t)(r0 + r)*C + (c0 + 4*tx));
        tile[r][4*tx+0] = v.x;
        tile[r][4*tx+1] = v.y;
        tile[r][4*tx+2] = v.z;
        tile[r][4*tx+3] = v.w;
    }
    __syncthreads();
#pragma unroll
    for (int k = 0; k < 4; k++) {
        const int r = ty + 16*k;
        float4 v;
        v.x = tile[4*tx+0][r];
        v.y = tile[4*tx+1][r];
        v.z = tile[4*tx+2][r];
        v.w = tile[4*tx+3][r];
        *(float4*)(out + (size_t)(c0 + r)*R + (r0 + 4*tx)) = v;
    }
}

// One-time host resources (handles only; launched work is identical per call).
static cudaStream_t g_s1, g_s2;
static cudaEvent_t  g_e_f10, g_e_f11, g_e_s2;
static bool         g_init_done = false;

static void ensure_init() {
    if (!g_init_done) {
        cudaStreamCreateWithFlags(&g_s1, cudaStreamNonBlocking);
        cudaStreamCreateWithFlags(&g_s2, cudaStreamNonBlocking);
        cudaEventCreateWithFlags(&g_e_f10, cudaEventDisableTiming);
        cudaEventCreateWithFlags(&g_e_f11, cudaEventDisableTiming);
        cudaEventCreateWithFlags(&g_e_s2,  cudaEventDisableTiming);
        g_init_done = true;
    }
}

extern "C" void kernel_launch(void* const* d_in, const int* in_sizes, int n_in,
                              void* d_out, int out_size) {
    const float*  x     = (const float*)d_in[0];
    const float2* expkM = (const float2*)d_in[1];
    const float2* expkN = (const float2*)d_in[2];
    const int M = in_sizes[1] / 2;            // 4096
    const int N = in_sizes[2] / 2;            // 4096
    float* out = (float*)d_out;

    ensure_init();

    float *scr1 = nullptr, *scr2 = nullptr;
    cudaGetSymbolAddress((void**)&scr1, g_scratch1);
    cudaGetSymbolAddress((void**)&scr2, g_scratch2);

    const size_t be = (size_t)M * (size_t)N;   // elements per batch
    const int HC = 2048;                       // chunk size along N
    dim3 tblk(256);
    dim3 t1grid(HC/64, M/64);                  // T1 chunk: 32 x 64 tiles
    dim3 t2grid(M/64, HC/64);                  // T2 chunk: 64 x 32 tiles

    // Chain per (b, x):  F1(b) -> T1h(b,x) -> F2h(b,x, in-place scr2) -> T2h(b,x -> d_out)
    // s0: chains (0,0), (1,0). s1: F1(1). s2: chains (0,1), (1,1).

    // ---- s0: F1(0) ----
    dct_fft_kernel<1><<<M, 128, 0, 0>>>(x, expkN, scr1);
    cudaEventRecord(g_e_f10, 0);

    // ---- s1: F1(1) ----
    cudaStreamWaitEvent(g_s1, g_e_f10, 0);
    dct_fft_kernel<1><<<M, 128, 0, g_s1>>>(x + be, expkN, scr1 + be);
    cudaEventRecord(g_e_f11, g_s1);

    // ---- s2: chunk-1 chains ----
    cudaStreamWaitEvent(g_s2, g_e_f10, 0);
    // (0,1)
    transpose_kernel<<<t1grid, tblk, 0, g_s2>>>(scr1, scr2, M, N, HC, 0);
    dct_fft_kernel<0><<<HC, 128, 0, g_s2>>>(scr2 + (size_t)HC*NN, expkM,
                                            scr2 + (size_t)HC*NN);
    transpose_kernel<<<t2grid, tblk, 0, g_s2>>>(scr2, out, N, M, 0, HC);
    // (1,1)
    cudaStreamWaitEvent(g_s2, g_e_f11, 0);
    transpose_kernel<<<t1grid, tblk, 0, g_s2>>>(scr1 + be, scr2 + be, M, N, HC, 0);
    dct_fft_kernel<0><<<HC, 128, 0, g_s2>>>(scr2 + be + (size_t)HC*NN, expkM,
                                            scr2 + be + (size_t)HC*NN);
    transpose_kernel<<<t2grid, tblk, 0, g_s2>>>(scr2 + be, out + be, N, M, 0, HC);
    cudaEventRecord(g_e_s2, g_s2);

    // ---- s0: chunk-0 chains ----
    // (0,0)
    transpose_kernel<<<t1grid, tblk, 0, 0>>>(scr1, scr2, M, N, 0, 0);
    dct_fft_kernel<0><<<HC, 128, 0, 0>>>(scr2, expkM, scr2);
    transpose_kernel<<<t2grid, tblk, 0, 0>>>(scr2, out, N, M, 0, 0);
    // (1,0)
    cudaStreamWaitEvent(0, g_e_f11, 0);
    transpose_kernel<<<t1grid, tblk, 0, 0>>>(scr1 + be, scr2 + be, M, N, 0, 0);
    dct_fft_kernel<0><<<HC, 128, 0, 0>>>(scr2 + be, expkM, scr2 + be);
    transpose_kernel<<<t2grid, tblk, 0, 0>>>(scr2 + be, out + be, N, M, 0, 0);

    // ---- join ----
    cudaStreamWaitEvent(0, g_e_s2, 0);
}